// round 1
// baseline (speedup 1.0000x reference)
#include <cuda_runtime.h>
#include <cuda_bf16.h>

// Problem constants (fixed by the reference)
#define WF 512.0f
#define HF 512.0f
#define NG 2048
#define NPAIR (NG / 2)
#define CHUNK_PAIRS 512           // 512 pairs * 16 floats * 4B = 32 KB smem tile
#define TPB 256

// Packed per-pair coefficients: for pair p (gaussians 2p, 2p+1):
// [P0,P1, Q0,Q1, R0,R1, NMX0,NMX1, NMY0,NMY1, CR0,CR1, CG0,CG1, CB0,CB1]
// P,Q,R already scaled by -log2(e); NMX/NMY = -mu in pixel units.
__device__ float g_coef[NPAIR * 16];

typedef unsigned long long u64;

__device__ __forceinline__ u64 f2add(u64 a, u64 b) {
    u64 r; asm("add.rn.f32x2 %0,%1,%2;" : "=l"(r) : "l"(a), "l"(b)); return r;
}
__device__ __forceinline__ u64 f2mul(u64 a, u64 b) {
    u64 r; asm("mul.rn.f32x2 %0,%1,%2;" : "=l"(r) : "l"(a), "l"(b)); return r;
}
__device__ __forceinline__ u64 f2fma(u64 a, u64 b, u64 c) {
    u64 r; asm("fma.rn.f32x2 %0,%1,%2,%3;" : "=l"(r) : "l"(a), "l"(b), "l"(c)); return r;
}
__device__ __forceinline__ u64 pk(float lo, float hi) {
    u64 r; asm("mov.b64 %0,{%1,%2};" : "=l"(r) : "f"(lo), "f"(hi)); return r;
}
__device__ __forceinline__ float2 upk(u64 v) {
    float2 o; asm("mov.b64 {%0,%1},%2;" : "=f"(o.x), "=f"(o.y) : "l"(v)); return o;
}
__device__ __forceinline__ float ex2(float x) {
    float r; asm("ex2.approx.ftz.f32 %0,%1;" : "=f"(r) : "f"(x)); return r;
}

// ---------------------------------------------------------------------------
// Precompute kernel: N gaussians -> packed quadratic coefficients + colors.
// All transcendentals (tanh/sin/cos/sigmoid) happen here ONCE per gaussian.
// ---------------------------------------------------------------------------
__global__ void precompute_kernel(const float* __restrict__ rgb,
                                  const float* __restrict__ mu,
                                  const float* __restrict__ scale,
                                  const float* __restrict__ angle,
                                  int n) {
    int i = blockIdx.x * blockDim.x + threadIdx.x;
    if (i >= n) return;

    const float MU_BORDER = 1.05f;
    const float PI_APPROX = 3.1416f;
    const float S_MIN = 1.0f / 30.0f;
    const float S_MAX = 1.0f / 0.75f;
    const float LOG2E = 1.4426950408889634f;

    // mu in pixel units: vec = x_px - (tanh(mu)*1.05 + 1) * 0.5 * wh
    float mpx = (tanhf(mu[2 * i + 0]) * MU_BORDER + 1.0f) * 0.5f * WF;
    float mpy = (tanhf(mu[2 * i + 1]) * MU_BORDER + 1.0f) * 0.5f * HF;

    float al = tanhf(angle[i]) * PI_APPROX;
    float c = cosf(al);
    float s = sinf(al);

    float S0 = 1.0f / (1.0f + expf(-scale[2 * i + 0])) * (S_MAX - S_MIN) + S_MIN;
    float S1 = 1.0f / (1.0f + expf(-scale[2 * i + 1])) * (S_MAX - S_MIN) + S_MIN;

    // d1x = S0*(c*vx - s*vy), d1y = S1*(s*vx + c*vy)
    float a = S0 * c, b = -S0 * s;
    float e = S1 * s, f = S1 * c;

    // q = d1x^2 + d1y^2 = P vx^2 + Q vx vy + R vy^2  ; fold -log2(e) for ex2
    float P = -LOG2E * (a * a + e * e);
    float Q = -LOG2E * 2.0f * (a * b + e * f);
    float R = -LOG2E * (b * b + f * f);

    float cr = 1.0f / (1.0f + expf(-rgb[3 * i + 0]));
    float cg = 1.0f / (1.0f + expf(-rgb[3 * i + 1]));
    float cb = 1.0f / (1.0f + expf(-rgb[3 * i + 2]));

    int p = i >> 1;
    int l = i & 1;
    float* base = g_coef + p * 16;
    base[0 + l]  = P;
    base[2 + l]  = Q;
    base[4 + l]  = R;
    base[6 + l]  = -mpx;
    base[8 + l]  = -mpy;
    base[10 + l] = cr;
    base[12 + l] = cg;
    base[14 + l] = cb;
}

// ---------------------------------------------------------------------------
// Main splat kernel: 1 pixel / thread, loops over gaussian pairs from smem.
// Inner loop per pair (2 gaussians): 10 packed-f32x2 FMA-pipe ops + 2 MUFU.
// ---------------------------------------------------------------------------
__global__ void __launch_bounds__(TPB) splat_kernel(const float* __restrict__ x,
                                                    float* __restrict__ out,
                                                    int B) {
    __shared__ float sc[CHUNK_PAIRS * 16];  // 32 KB

    int pix = blockIdx.x * TPB + threadIdx.x;
    bool valid = pix < B;

    float px = 0.0f, py = 0.0f;
    if (valid) {
        float2 xy = ((const float2*)x)[pix];
        px = xy.x; py = xy.y;
    }
    u64 px2 = pk(px, px);
    u64 py2 = pk(py, py);

    u64 aR = 0ull, aG = 0ull, aB = 0ull;  // packed (0.f, 0.f) accumulators

    for (int c0 = 0; c0 < NPAIR; c0 += CHUNK_PAIRS) {
        __syncthreads();
        // cooperative tile load: 32KB via float4
        const float4* gsrc = (const float4*)(g_coef + c0 * 16);
        for (int i = threadIdx.x; i < CHUNK_PAIRS * 16 / 4; i += TPB) {
            ((float4*)sc)[i] = gsrc[i];
        }
        __syncthreads();

#pragma unroll 4
        for (int p = 0; p < CHUNK_PAIRS; p++) {
            const ulonglong2* sp = (const ulonglong2*)(sc + p * 16);
            ulonglong2 c01 = sp[0];   // {P2, Q2}
            ulonglong2 c23 = sp[1];   // {R2, NMX2}
            ulonglong2 c45 = sp[2];   // {NMY2, CR2}
            ulonglong2 c67 = sp[3];   // {CG2, CB2}

            u64 vx = f2add(px2, c23.y);                 // x - mx
            u64 vy = f2add(py2, c45.x);                 // y - my
            u64 t1 = f2fma(c01.y, vy, f2mul(c01.x, vx)); // Q*vy + P*vx
            u64 q  = f2fma(vx, t1, f2mul(f2mul(c23.x, vy), vy)); // vx*t1 + R*vy^2

            float2 qq = upk(q);
            u64 w = pk(ex2(qq.x), ex2(qq.y));

            aR = f2fma(w, c45.y, aR);
            aG = f2fma(w, c67.x, aG);
            aB = f2fma(w, c67.y, aB);
        }
    }

    if (valid) {
        float2 r = upk(aR), g = upk(aG), b = upk(aB);
        out[3 * pix + 0] = r.x + r.y;
        out[3 * pix + 1] = g.x + g.y;
        out[3 * pix + 2] = b.x + b.y;
    }
}

// ---------------------------------------------------------------------------
// Launch: inputs in metadata order: x[B,2], rgb[N,3], mu[N,2], scale[N,2], angle[N]
// ---------------------------------------------------------------------------
extern "C" void kernel_launch(void* const* d_in, const int* in_sizes, int n_in,
                              void* d_out, int out_size) {
    const float* x     = (const float*)d_in[0];
    const float* rgb   = (const float*)d_in[1];
    const float* mu    = (const float*)d_in[2];
    const float* scale = (const float*)d_in[3];
    const float* angle = (const float*)d_in[4];
    float* out = (float*)d_out;

    int N = in_sizes[4];          // 2048
    int B = in_sizes[0] / 2;      // 65536

    precompute_kernel<<<(N + 255) / 256, 256>>>(rgb, mu, scale, angle, N);
    splat_kernel<<<(B + TPB - 1) / TPB, TPB>>>(x, out, B);
}

// round 2
// speedup vs baseline: 1.0530x; 1.0530x over previous
#include <cuda_runtime.h>
#include <cuda_bf16.h>

// Problem constants (fixed by the reference)
#define WF 512.0f
#define HF 512.0f
#define NG 2048
#define NPAIR (NG / 2)
#define CHUNK_PAIRS 512           // 512 pairs * 16 floats * 4B = 32 KB smem tile
#define TPB 256
#define PIX 2                      // pixels per thread

// Packed per-pair coefficients: for pair p (gaussians 2p, 2p+1):
// [P0,P1, Q0,Q1, R0,R1, NMX0,NMX1, NMY0,NMY1, CR0,CR1, CG0,CG1, CB0,CB1]
// P,Q,R already scaled by -log2(e); NMX/NMY = -mu in pixel units.
__device__ float g_coef[NPAIR * 16];

typedef unsigned long long u64;

__device__ __forceinline__ u64 f2add(u64 a, u64 b) {
    u64 r; asm("add.rn.f32x2 %0,%1,%2;" : "=l"(r) : "l"(a), "l"(b)); return r;
}
__device__ __forceinline__ u64 f2mul(u64 a, u64 b) {
    u64 r; asm("mul.rn.f32x2 %0,%1,%2;" : "=l"(r) : "l"(a), "l"(b)); return r;
}
__device__ __forceinline__ u64 f2fma(u64 a, u64 b, u64 c) {
    u64 r; asm("fma.rn.f32x2 %0,%1,%2,%3;" : "=l"(r) : "l"(a), "l"(b), "l"(c)); return r;
}
__device__ __forceinline__ u64 pk(float lo, float hi) {
    u64 r; asm("mov.b64 %0,{%1,%2};" : "=l"(r) : "f"(lo), "f"(hi)); return r;
}
__device__ __forceinline__ float2 upk(u64 v) {
    float2 o; asm("mov.b64 {%0,%1},%2;" : "=f"(o.x), "=f"(o.y) : "l"(v)); return o;
}
__device__ __forceinline__ float ex2(float x) {
    float r; asm("ex2.approx.ftz.f32 %0,%1;" : "=f"(r) : "f"(x)); return r;
}

// ---------------------------------------------------------------------------
// Precompute kernel: N gaussians -> packed quadratic coefficients + colors.
// All transcendentals (tanh/sin/cos/sigmoid) happen here ONCE per gaussian.
// ---------------------------------------------------------------------------
__global__ void precompute_kernel(const float* __restrict__ rgb,
                                  const float* __restrict__ mu,
                                  const float* __restrict__ scale,
                                  const float* __restrict__ angle,
                                  int n) {
    int i = blockIdx.x * blockDim.x + threadIdx.x;
    if (i >= n) return;

    const float MU_BORDER = 1.05f;
    const float PI_APPROX = 3.1416f;
    const float S_MIN = 1.0f / 30.0f;
    const float S_MAX = 1.0f / 0.75f;
    const float LOG2E = 1.4426950408889634f;

    // mu in pixel units: vec = x_px - (tanh(mu)*1.05 + 1) * 0.5 * wh
    float mpx = (tanhf(mu[2 * i + 0]) * MU_BORDER + 1.0f) * 0.5f * WF;
    float mpy = (tanhf(mu[2 * i + 1]) * MU_BORDER + 1.0f) * 0.5f * HF;

    float al = tanhf(angle[i]) * PI_APPROX;
    float c = cosf(al);
    float s = sinf(al);

    float S0 = 1.0f / (1.0f + expf(-scale[2 * i + 0])) * (S_MAX - S_MIN) + S_MIN;
    float S1 = 1.0f / (1.0f + expf(-scale[2 * i + 1])) * (S_MAX - S_MIN) + S_MIN;

    // d1x = S0*(c*vx - s*vy), d1y = S1*(s*vx + c*vy)
    float a = S0 * c, b = -S0 * s;
    float e = S1 * s, f = S1 * c;

    // q = d1x^2 + d1y^2 = P vx^2 + Q vx vy + R vy^2  ; fold -log2(e) for ex2
    float P = -LOG2E * (a * a + e * e);
    float Q = -LOG2E * 2.0f * (a * b + e * f);
    float R = -LOG2E * (b * b + f * f);

    float cr = 1.0f / (1.0f + expf(-rgb[3 * i + 0]));
    float cg = 1.0f / (1.0f + expf(-rgb[3 * i + 1]));
    float cb = 1.0f / (1.0f + expf(-rgb[3 * i + 2]));

    int p = i >> 1;
    int l = i & 1;
    float* base = g_coef + p * 16;
    base[0 + l]  = P;
    base[2 + l]  = Q;
    base[4 + l]  = R;
    base[6 + l]  = -mpx;
    base[8 + l]  = -mpy;
    base[10 + l] = cr;
    base[12 + l] = cg;
    base[14 + l] = cb;
}

// ---------------------------------------------------------------------------
// Main splat kernel: 2 pixels / thread. The 64B/pair smem read is amortized
// over both pixels, halving LDS traffic per FLOP vs round 1.
// grid = B/(2*TPB) = 128 blocks -> <=1 block/SM, no wave quantization.
// ---------------------------------------------------------------------------
__global__ void __launch_bounds__(TPB) splat_kernel(const float* __restrict__ x,
                                                    float* __restrict__ out,
                                                    int B) {
    __shared__ float sc[CHUNK_PAIRS * 16];  // 32 KB

    int half = B >> 1;                       // 32768
    int t = blockIdx.x * TPB + threadIdx.x;  // [0, half)
    int p0 = t;
    int p1 = t + half;
    bool v0 = p0 < B, v1 = p1 < B;

    float ax = 0.f, ay = 0.f, bx = 0.f, by = 0.f;
    if (v0) { float2 xy = ((const float2*)x)[p0]; ax = xy.x; ay = xy.y; }
    if (v1) { float2 xy = ((const float2*)x)[p1]; bx = xy.x; by = xy.y; }

    u64 ax2 = pk(ax, ax), ay2 = pk(ay, ay);
    u64 bx2 = pk(bx, bx), by2 = pk(by, by);

    // packed (lo,hi) accumulators for each pixel's RGB
    u64 aR = 0ull, aG = 0ull, aB = 0ull;
    u64 bR = 0ull, bG = 0ull, bB = 0ull;

    for (int c0 = 0; c0 < NPAIR; c0 += CHUNK_PAIRS) {
        __syncthreads();
        const float4* gsrc = (const float4*)(g_coef + c0 * 16);
        for (int i = threadIdx.x; i < CHUNK_PAIRS * 16 / 4; i += TPB) {
            ((float4*)sc)[i] = gsrc[i];
        }
        __syncthreads();

#pragma unroll 4
        for (int p = 0; p < CHUNK_PAIRS; p++) {
            const ulonglong2* sp = (const ulonglong2*)(sc + p * 16);
            ulonglong2 c01 = sp[0];   // {P2, Q2}
            ulonglong2 c23 = sp[1];   // {R2, NMX2}
            ulonglong2 c45 = sp[2];   // {NMY2, CR2}
            ulonglong2 c67 = sp[3];   // {CG2, CB2}

            // ---- pixel 0 ----
            {
                u64 vx = f2add(ax2, c23.y);
                u64 vy = f2add(ay2, c45.x);
                u64 t1 = f2fma(c01.y, vy, f2mul(c01.x, vx));      // P*vx + Q*vy
                u64 q  = f2fma(vx, t1, f2mul(f2mul(c23.x, vy), vy));
                float2 qq = upk(q);
                u64 w = pk(ex2(qq.x), ex2(qq.y));
                aR = f2fma(w, c45.y, aR);
                aG = f2fma(w, c67.x, aG);
                aB = f2fma(w, c67.y, aB);
            }
            // ---- pixel 1 ----
            {
                u64 vx = f2add(bx2, c23.y);
                u64 vy = f2add(by2, c45.x);
                u64 t1 = f2fma(c01.y, vy, f2mul(c01.x, vx));
                u64 q  = f2fma(vx, t1, f2mul(f2mul(c23.x, vy), vy));
                float2 qq = upk(q);
                u64 w = pk(ex2(qq.x), ex2(qq.y));
                bR = f2fma(w, c45.y, bR);
                bG = f2fma(w, c67.x, bG);
                bB = f2fma(w, c67.y, bB);
            }
        }
    }

    if (v0) {
        float2 r = upk(aR), g = upk(aG), b = upk(aB);
        out[3 * p0 + 0] = r.x + r.y;
        out[3 * p0 + 1] = g.x + g.y;
        out[3 * p0 + 2] = b.x + b.y;
    }
    if (v1) {
        float2 r = upk(bR), g = upk(bG), b = upk(bB);
        out[3 * p1 + 0] = r.x + r.y;
        out[3 * p1 + 1] = g.x + g.y;
        out[3 * p1 + 2] = b.x + b.y;
    }
}

// ---------------------------------------------------------------------------
// Launch: inputs in metadata order: x[B,2], rgb[N,3], mu[N,2], scale[N,2], angle[N]
// ---------------------------------------------------------------------------
extern "C" void kernel_launch(void* const* d_in, const int* in_sizes, int n_in,
                              void* d_out, int out_size) {
    const float* x     = (const float*)d_in[0];
    const float* rgb   = (const float*)d_in[1];
    const float* mu    = (const float*)d_in[2];
    const float* scale = (const float*)d_in[3];
    const float* angle = (const float*)d_in[4];
    float* out = (float*)d_out;

    int N = in_sizes[4];          // 2048
    int B = in_sizes[0] / 2;      // 65536

    precompute_kernel<<<(N + 255) / 256, 256>>>(rgb, mu, scale, angle, N);

    int threads = (B + PIX - 1) / PIX;                 // 32768
    int blocks = (threads + TPB - 1) / TPB;            // 128
    splat_kernel<<<blocks, TPB>>>(x, out, B);
}